// round 7
// baseline (speedup 1.0000x reference)
#include <cuda_runtime.h>

#define RES 256
#define CELLS (RES*RES)
#define NCH 32
#define ACCSZ (CELLS*NCH)
#define NPLANE 3
#define FULLMASK 0xFFFFFFFFu

// Scratch (device globals: allocation-free rule)
__device__ float  g_acc [NPLANE*ACCSZ];   // [plane][cell][ch]
__device__ float  g_cnt [NPLANE*CELLS];   // [plane][cell]
__device__ float  g_newT[NPLANE*ACCSZ];   // [plane][ch][cell]  (transposed, /count)
__device__ double g_sum [NPLANE];
__device__ double g_ss  [NPLANE];

// ---------------------------------------------------------------- zero (float4)
__global__ void k_zero() {
    int i = blockIdx.x * blockDim.x + threadIdx.x;
    int stride = gridDim.x * blockDim.x;
    float4 z = make_float4(0.f, 0.f, 0.f, 0.f);
    float4* a = (float4*)g_acc;
    float4* c = (float4*)g_cnt;
    for (int j = i; j < NPLANE*ACCSZ/4; j += stride) a[j] = z;
    for (int j = i; j < NPLANE*CELLS/4; j += stride) c[j] = z;
    if (i < NPLANE) { g_sum[i] = 0.0; g_ss[i] = 0.0; }
}

// ---------------------------------------------------------------- scatter
// one warp per gaussian; lane = channel. 4 coalesced 128B RED lines per plane.
__global__ void k_scatter(const float* __restrict__ xyz,
                          const float* __restrict__ feats, int n) {
    int w    = (blockIdx.x * blockDim.x + threadIdx.x) >> 5;
    int lane = threadIdx.x & 31;
    if (w >= n) return;

    float gx = __ldg(xyz + 3*w + 0);
    float gy = __ldg(xyz + 3*w + 1);
    float gz = __ldg(xyz + 3*w + 2);
    float x = fminf(fmaxf((gx + 1.f) * 0.5f, 0.f), 0.999f) * (float)(RES - 1);
    float y = fminf(fmaxf((gy + 1.f) * 0.5f, 0.f), 0.999f) * (float)(RES - 1);
    float z = fminf(fmaxf((gz + 1.f) * 0.5f, 0.f), 0.999f) * (float)(RES - 1);

    #pragma unroll
    for (int p = 0; p < 3; p++) {
        float px = (p == 2) ? y : x;              // xy:(x,y) xz:(x,z) yz:(y,z)
        float py = (p == 0) ? y : z;

        int ix0 = (int)floorf(px);
        int iy0 = (int)floorf(py);
        int ix0c = min(max(ix0, 0), RES-1);
        int ix1c = min(ix0 + 1,    RES-1);
        int iy0c = min(max(iy0, 0), RES-1);
        int iy1c = min(iy0 + 1,    RES-1);

        float wx0 = fminf(fmaxf((float)ix1c - px, 0.f), 1.f);
        float wx1 = fminf(fmaxf(px - (float)ix0c, 0.f), 1.f);
        float wy0 = fminf(fmaxf((float)iy1c - py, 0.f), 1.f);
        float wy1 = fminf(fmaxf(py - (float)iy0c, 0.f), 1.f);

        int l0 = iy0c*RES + ix0c;
        int l1 = iy1c*RES + ix0c;
        int l2 = iy0c*RES + ix1c;
        int l3 = iy1c*RES + ix1c;
        float w00 = wx0*wy0, w01 = wx0*wy1, w10 = wx1*wy0, w11 = wx1*wy1;

        float f = __ldg(feats + (size_t)w*96 + p*32 + lane);
        float* base = g_acc + (size_t)p*ACCSZ;
        atomicAdd(base + (size_t)l0*NCH + lane, f*w00);
        atomicAdd(base + (size_t)l1*NCH + lane, f*w01);
        atomicAdd(base + (size_t)l2*NCH + lane, f*w10);
        atomicAdd(base + (size_t)l3*NCH + lane, f*w11);

        if (lane < 4) {
            int ll = (lane == 0) ? l0 : (lane == 1) ? l1 : (lane == 2) ? l2 : l3;
            atomicAdd(g_cnt + p*CELLS + ll, 1.0f);
        }
    }
}

// ---------------------------------------------------------------- reduce + transpose
__global__ void k_reduce() {
    int p    = blockIdx.y;
    int cell = blockIdx.x * blockDim.x + threadIdx.x;

    float cnt = g_cnt[p*CELLS + cell];
    float inv = 1.f / (cnt + 1e-6f);
    const float4* a = (const float4*)(g_acc + (size_t)p*ACCSZ + (size_t)cell*NCH);
    float* nt = g_newT + (size_t)p*ACCSZ;

    float s = 0.f, ss = 0.f;
    #pragma unroll
    for (int i = 0; i < 8; i++) {
        float4 v = a[i];
        float n0 = v.x*inv, n1 = v.y*inv, n2 = v.z*inv, n3 = v.w*inv;
        s  += n0 + n1 + n2 + n3;
        ss += n0*n0 + n1*n1 + n2*n2 + n3*n3;
        nt[(size_t)(i*4+0)*CELLS + cell] = n0;
        nt[(size_t)(i*4+1)*CELLS + cell] = n1;
        nt[(size_t)(i*4+2)*CELLS + cell] = n2;
        nt[(size_t)(i*4+3)*CELLS + cell] = n3;
    }

    double ds = (double)s, dss = (double)ss;
    #pragma unroll
    for (int off = 16; off; off >>= 1) {
        ds  += __shfl_down_sync(FULLMASK, ds,  off);
        dss += __shfl_down_sync(FULLMASK, dss, off);
    }
    __shared__ double shs[8], shss[8];
    int wid = threadIdx.x >> 5;
    if ((threadIdx.x & 31) == 0) { shs[wid] = ds; shss[wid] = dss; }
    __syncthreads();
    if (threadIdx.x == 0) {
        double t = 0.0, tt = 0.0;
        for (int i = 0; i < 8; i++) { t += shs[i]; tt += shss[i]; }
        atomicAdd(&g_sum[p], t);
        atomicAdd(&g_ss[p], tt);
    }
}

// ---------------------------------------------------------------- normalize + blur + residual
// Warp-autonomous: one warp = one (plane, ch, 32x32 tile). Horizontal 5-tap
// via shfl (lanes 0,1,30,31 fetch the 4 halo px), vertical 5-tap in a rolling
// register window. No smem, no __syncthreads.
#define STRIP 32
__global__ void k_blur(const float* __restrict__ p_xy,
                       const float* __restrict__ p_xz,
                       const float* __restrict__ p_yz,
                       const float* __restrict__ lnw,
                       const float* __restrict__ lnb,
                       float* __restrict__ out) {
    const float W0 = 0.054488684549642945f;
    const float W1 = 0.2442013422000340f;
    const float W2 = 0.4026199464998460f;

    int gw   = (blockIdx.x * blockDim.x + threadIdx.x) >> 5;  // 0..6143
    int lane = threadIdx.x & 31;

    int pc  = gw >> 6;        // plane*32 + ch
    int rem = gw & 63;
    int ys  = rem >> 3;       // y strip 0..7
    int xs  = rem & 7;        // x segment 0..7
    int p   = pc >> 5;
    int c   = pc & 31;

    double nelem = (double)ACCSZ;
    double mu_d  = g_sum[p] / nelem;
    double var_d = g_ss[p] / nelem - mu_d * mu_d;
    float mu  = (float)mu_d;
    float inv = (float)(1.0 / sqrt(var_d + 1e-5));

    const float* nt    = g_newT + (size_t)p*ACCSZ + (size_t)c*CELLS;
    const float* lw    = lnw + (size_t)c*CELLS;
    const float* lb    = lnb + (size_t)c*CELLS;
    const float* plane = ((p == 0) ? p_xy : (p == 1) ? p_xz : p_yz) + (size_t)c*CELLS;
    float*       o     = out + (size_t)p*ACCSZ + (size_t)c*CELLS;

    int x0 = xs * STRIP;
    int x  = x0 + lane;
    // halo pixel handled by this lane (lanes 0,1 -> left, 30,31 -> right)
    int  hx     = (lane < 2) ? (x0 - 2 + lane) : (x0 + 2 + lane);
    bool hvalid = (lane < 2) ? (hx >= 0) : ((lane >= 30) && (hx < RES));

    int y0 = ys * STRIP;

    // LN'd load pair for row y (main + halo), zero outside image
    auto loadrow = [&](int y, float& v, float& h) {
        v = 0.f; h = 0.f;
        if ((unsigned)y < (unsigned)RES) {
            int lin = y*RES + x;
            v = (nt[lin] - mu) * inv * lw[lin] + lb[lin];
            if (hvalid) {
                int hl = y*RES + hx;
                h = (nt[hl] - mu) * inv * lw[hl] + lb[hl];
            }
        }
    };

    // 2-deep prefetch
    float vA, hA, vB, hB;
    loadrow(y0 - 2, vA, hA);
    loadrow(y0 - 1, vB, hB);

    float r0 = 0.f, r1 = 0.f, r2 = 0.f, r3 = 0.f, r4 = 0.f;

    #pragma unroll 4
    for (int i = 0; i < STRIP + 4; i++) {
        int y = y0 - 2 + i;
        float v = vA, h = hA;
        vA = vB; hA = hB;
        loadrow(y + 2, vB, hB);

        // horizontal 5-tap via shfl
        float um1 = __shfl_up_sync  (FULLMASK, v, 1);
        float um2 = __shfl_up_sync  (FULLMASK, v, 2);
        float dp1 = __shfl_down_sync(FULLMASK, v, 1);
        float dp2 = __shfl_down_sync(FULLMASK, v, 2);
        float lv0 = __shfl_sync(FULLMASK, h, 0);
        float lv1 = __shfl_sync(FULLMASK, h, 1);
        float rv0 = __shfl_sync(FULLMASK, h, 30);
        float rv1 = __shfl_sync(FULLMASK, h, 31);

        float vm1 = (lane == 0)  ? lv1 : um1;
        float vm2 = (lane == 0)  ? lv0 : ((lane == 1)  ? lv1 : um2);
        float vp1 = (lane == 31) ? rv0 : dp1;
        float vp2 = (lane == 31) ? rv1 : ((lane == 30) ? rv0 : dp2);

        float hrow = W0*(vm2 + vp2) + W1*(vm1 + vp1) + W2*v;

        r0 = r1; r1 = r2; r2 = r3; r3 = r4; r4 = hrow;

        if (i >= 4) {
            int yo  = y - 2;
            int lin = yo*RES + x;
            float r = W0*(r0 + r4) + W1*(r1 + r3) + W2*r2;
            o[lin] = r + plane[lin];
        }
    }
}

// ---------------------------------------------------------------- launch
extern "C" void kernel_launch(void* const* d_in, const int* in_sizes, int n_in,
                              void* d_out, int out_size) {
    const float* plane_xy = (const float*)d_in[0];
    const float* plane_xz = (const float*)d_in[1];
    const float* plane_yz = (const float*)d_in[2];
    const float* ln_w     = (const float*)d_in[3];
    const float* ln_b     = (const float*)d_in[4];
    const float* feats    = (const float*)d_in[5];
    const float* xyz      = (const float*)d_in[6];
    float* out = (float*)d_out;
    int n = in_sizes[6] / 3;   // 500000

    k_zero<<<1024, 256>>>();
    {
        int threads = 256;
        long long total = (long long)n * 32;
        int blocks = (int)((total + threads - 1) / threads);
        k_scatter<<<blocks, threads>>>(xyz, feats, n);
    }
    k_reduce<<<dim3(CELLS/256, NPLANE), 256>>>();
    // 6144 warps = 3 planes x 32 ch x 8 ystrips x 8 xsegs; 8 warps/block
    k_blur<<<768, 256>>>(plane_xy, plane_xz, plane_yz, ln_w, ln_b, out);
}